// round 14
// baseline (speedup 1.0000x reference)
#include <cuda_runtime.h>
#include <cuda_fp16.h>
#include <cstdint>

// ============================================================================
// LowRankBilinearFusion, HMMA fp16:
//   prep: Wu,Wv,Wp -> fp16 (weights only; u/v converted inside proj)
//   proj: up16 = u@Wu^T (fp32 A cvt in-kernel); vp_part = v@Wv^T k-split x2
//   add:  vp16 = fp16(part0+part1)
//   fuse: out[bm,n0] = relu(vp16[b] @ (up16[bm] ⊙ Wp16[n0])^T + bp)
//     256 thr, 8 warps (2x4), warp tile 64x32, 2 CTAs/SM.
//     A = RAW vp16 resident; up16 applied to B FRAGMENTS in registers.
//     Inner loop: B LDSM first (longest dep chain), hoisted swizzle bases.
// ============================================================================

__device__ float  g_vp_part[2 * 4096 * 256];
__device__ __half g_up16[1024 * 256];
__device__ __half g_vp16[4096 * 256];
__device__ __half g_wu16[256 * 1024];
__device__ __half g_wv16[256 * 2048];
__device__ __half g_wp16[256 * 256];

#define SWZ(o) ((o) ^ (((o) >> 3) & 0x70))

__device__ __forceinline__ uint32_t smem_u32(const void* p) {
    uint32_t a;
    asm("{ .reg .u64 t; cvta.to.shared.u64 t, %1; cvt.u32.u64 %0, t; }" : "=r"(a) : "l"(p));
    return a;
}
__device__ __forceinline__ void ldsm4(uint32_t& r0, uint32_t& r1, uint32_t& r2, uint32_t& r3,
                                      uint32_t addr) {
    asm volatile("ldmatrix.sync.aligned.m8n8.x4.shared.b16 {%0,%1,%2,%3}, [%4];"
                 : "=r"(r0), "=r"(r1), "=r"(r2), "=r"(r3) : "r"(addr));
}
__device__ __forceinline__ void mma_f16(float* c, const uint32_t* a, const uint32_t* b) {
    asm volatile(
        "mma.sync.aligned.m16n8k16.row.col.f32.f16.f16.f32 "
        "{%0,%1,%2,%3}, {%4,%5,%6,%7}, {%8,%9}, {%0,%1,%2,%3};"
        : "+f"(c[0]), "+f"(c[1]), "+f"(c[2]), "+f"(c[3])
        : "r"(a[0]), "r"(a[1]), "r"(a[2]), "r"(a[3]), "r"(b[0]), "r"(b[1]));
}
__device__ __forceinline__ void cp16(uint32_t dst, const void* src) {
    asm volatile("cp.async.cg.shared.global [%0], [%1], 16;" :: "r"(dst), "l"(src));
}
__device__ __forceinline__ void cp_commit() { asm volatile("cp.async.commit_group;" ::: "memory"); }
template <int N>
__device__ __forceinline__ void cp_wait() { asm volatile("cp.async.wait_group %0;" :: "n"(N) : "memory"); }
__device__ __forceinline__ uint32_t hmul2u(uint32_t a, __half2 m) {
    __half2 r = __hmul2(*(__half2*)&a, m);
    return *(uint32_t*)&r;
}
__device__ __forceinline__ uint32_t packh2(float a, float b) {
    __half2 h = __floats2half2_rn(a, b);
    return *(uint32_t*)&h;
}

// -------------------- prep: convert WEIGHTS to fp16 --------------------------
__global__ void __launch_bounds__(256) prep_cvt(
    const float* __restrict__ Wu, const float* __restrict__ Wv, const float* __restrict__ Wp,
    __half* wu, __half* wv, __half* wp)
{
    const int N3 = 256 * 1024, N4 = 256 * 2048, N5 = 256 * 256;
    int t = blockIdx.x * 256 + threadIdx.x;
    size_t i = (size_t)t * 4;
    const float* src; __half* dst; size_t j;
    if (i < N3)                    { src = Wu; dst = wu; j = i; }
    else if (i < (size_t)N3 + N4)  { src = Wv; dst = wv; j = i - N3; }
    else if (i < (size_t)N3 + N4 + N5) { src = Wp; dst = wp; j = i - N3 - N4; }
    else return;
    float4 x = *(const float4*)(src + j);
    uint2 o; o.x = packh2(x.x, x.y); o.y = packh2(x.z, x.w);
    *(uint2*)(dst + j) = o;
}

// ============================================================================
// proj: C[128x128] = A @ B16^T, A fp32 converted in-register. K=1024/CTA.
// Grid: 0..15 up (mt8 x n2) -> up16 direct; 16..143 vp (mt32 x n2 x kh2).
// Pipeline: LDG A(kc+1) + cp.async B(kc+1) -> MMA(kc) -> cvt+STS A(kc+1).
// 256 thr, 8 warps 2x4, warp tile 64x32. 2 CTAs/SM.
// ============================================================================
__global__ void __launch_bounds__(256, 2) proj_mma(
    const float* __restrict__ u, const float* __restrict__ v,
    const __half* __restrict__ wu, const __half* __restrict__ wv,
    __half* __restrict__ up16, float* __restrict__ vp_part)
{
    extern __shared__ char dsm[];
    uint32_t sb_raw = smem_u32(dsm);
    uint32_t sb = (sb_raw + 1023u) & ~1023u;
    char* smp = dsm + (sb - sb_raw);

    constexpr uint32_t BUF = 32768, OFF_B = 16384;

    const int bid = blockIdx.x;
    const int tid = threadIdx.x;
    const int wid = tid >> 5, lane = tid & 31;
    const int wm = (wid >> 2) * 64, wn = (wid & 3) * 32;

    const float* A; const __half* B;
    int lda, ldb;
    bool is_up;
    __half* Ch = nullptr; float* Cf = nullptr;
    if (bid < 16) {
        int mt = bid >> 1, n0 = bid & 1;
        A = u + (size_t)mt * 128 * 1024; lda = 1024;
        B = wu + (size_t)n0 * 128 * 1024; ldb = 1024;
        Ch = up16 + (size_t)mt * 128 * 256 + n0 * 128;
        is_up = true;
    } else {
        int b2 = bid - 16;
        int mt = b2 >> 2, n0 = (b2 >> 1) & 1, kh = b2 & 1;
        A = v + (size_t)mt * 128 * 2048 + kh * 1024; lda = 2048;
        B = wv + (size_t)n0 * 128 * 2048 + kh * 1024; ldb = 2048;
        Cf = vp_part + (size_t)kh * 4096 * 256 + (size_t)mt * 128 * 256 + n0 * 128;
        is_up = false;
    }

    const int row = tid >> 1, seg = tid & 1;
    const float* pA = A + (size_t)row * lda + seg * 32;
    const __half* pB = B + (size_t)row * ldb + seg * 32;
    const uint32_t rowoff = (uint32_t)(row * 128 + seg * 64);

    float c[4][4][4];
#pragma unroll
    for (int i = 0; i < 4; i++)
#pragma unroll
        for (int j = 0; j < 4; j++)
#pragma unroll
            for (int q = 0; q < 4; q++) c[i][j][q] = 0.f;

    float4 xa[8];
    auto loadA = [&](int kc) {
#pragma unroll
        for (int j = 0; j < 8; j++) xa[j] = *(const float4*)(pA + kc * 64 + j * 4);
    };
    auto storeA = [&](int bf) {
        char* p = smp + (uint32_t)bf * BUF;
#pragma unroll
        for (int i = 0; i < 4; i++) {
            uint4 w;
            w.x = packh2(xa[2 * i].x, xa[2 * i].y);
            w.y = packh2(xa[2 * i].z, xa[2 * i].w);
            w.z = packh2(xa[2 * i + 1].x, xa[2 * i + 1].y);
            w.w = packh2(xa[2 * i + 1].z, xa[2 * i + 1].w);
            *(uint4*)(p + SWZ(rowoff + i * 16)) = w;
        }
    };
    auto issueB = [&](int kc, int bf) {
        uint32_t base = sb + (uint32_t)bf * BUF;
#pragma unroll
        for (int j = 0; j < 4; j++)
            cp16(base + OFF_B + SWZ(rowoff + j * 16), pB + kc * 64 + j * 8);
    };
    auto mmas = [&](int bf) {
        uint32_t base = sb + (uint32_t)bf * BUF;
#pragma unroll
        for (int ks = 0; ks < 4; ks++) {
            uint32_t a[4][4], bfr[4][2];
            const uint32_t acol = (uint32_t)(ks * 32 + (lane >> 4) * 16);
#pragma unroll
            for (int np = 0; np < 2; np++) {
                uint32_t ro = (uint32_t)((wn + np * 16 + (lane & 15)) * 128) + acol;
                uint32_t m0, m1, m2, m3;
                ldsm4(m0, m1, m2, m3, base + OFF_B + SWZ(ro));
                bfr[2 * np][0] = m0; bfr[2 * np][1] = m2;
                bfr[2 * np + 1][0] = m1; bfr[2 * np + 1][1] = m3;
            }
#pragma unroll
            for (int mi = 0; mi < 4; mi++) {
                uint32_t ro = (uint32_t)((wm + mi * 16 + (lane & 15)) * 128) + acol;
                ldsm4(a[mi][0], a[mi][1], a[mi][2], a[mi][3], base + SWZ(ro));
            }
#pragma unroll
            for (int mi = 0; mi < 4; mi++)
#pragma unroll
                for (int nj = 0; nj < 4; nj++)
                    mma_f16(c[mi][nj], a[mi], bfr[nj]);
        }
    };

    loadA(0);
    issueB(0, 0); cp_commit();
    storeA(0);
    cp_wait<0>();
    __syncthreads();
    for (int kc = 0; kc < 16; kc++) {
        if (kc < 15) { loadA(kc + 1); issueB(kc + 1, (kc + 1) & 1); cp_commit(); }
        mmas(kc & 1);
        if (kc < 15) { storeA((kc + 1) & 1); cp_wait<0>(); }
        __syncthreads();
    }

    const int rin = lane >> 2, cin = (lane & 3) * 2;
    if (is_up) {
#pragma unroll
        for (int mi = 0; mi < 4; mi++)
#pragma unroll
            for (int nj = 0; nj < 4; nj++) {
                __half* p0 = Ch + (size_t)(wm + mi * 16 + rin) * 256 + wn + nj * 8 + cin;
                __half2 h0 = __floats2half2_rn(c[mi][nj][0], c[mi][nj][1]);
                __half2 h1 = __floats2half2_rn(c[mi][nj][2], c[mi][nj][3]);
                *(__half2*)p0 = h0;
                *(__half2*)(p0 + 8 * 256) = h1;
            }
    } else {
#pragma unroll
        for (int mi = 0; mi < 4; mi++)
#pragma unroll
            for (int nj = 0; nj < 4; nj++) {
                float* p0 = Cf + (size_t)(wm + mi * 16 + rin) * 256 + wn + nj * 8 + cin;
                *(float2*)p0 = make_float2(c[mi][nj][0], c[mi][nj][1]);
                *(float2*)(p0 + 8 * 256) = make_float2(c[mi][nj][2], c[mi][nj][3]);
            }
    }
}

// -------------------- add: vp16 = fp16(part0 + part1) ------------------------
__global__ void __launch_bounds__(256) add_parts(
    const float* __restrict__ vpp, __half* __restrict__ vp16)
{
    size_t i = ((size_t)blockIdx.x * 256 + threadIdx.x) * 4;
    float4 a = *(const float4*)(vpp + i);
    float4 b = *(const float4*)(vpp + (size_t)4096 * 256 + i);
    uint2 o;
    o.x = packh2(a.x + b.x, a.y + b.y);
    o.y = packh2(a.z + b.z, a.w + b.w);
    *(uint2*)(vp16 + i) = o;
}

// ============================================================================
// fuse: out[bm, n0] = relu(vp16[b] @ (up16[bm] ⊙ Wp16[n0])^T + bp)
// 128 x 128 per CTA, K=256. 256 threads, 8 warps (2x4), warp tile 64x32.
// A = raw vp16 resident, progressive groups (A0,B0),(A1,B1),(A2),(A3).
// up16 applied to B fragments; B LDSM issued FIRST (longest chain).
// addr = base + ra + (acol ^ sz). 2 CTAs/SM.
// ============================================================================
__global__ void __launch_bounds__(256, 2) fuse_mma(
    const __half* __restrict__ up16, const __half* __restrict__ vp16,
    const __half* __restrict__ wp, const float* __restrict__ bp,
    float* __restrict__ out)
{
    extern __shared__ char dsm[];
    uint32_t sb_raw = smem_u32(dsm);
    uint32_t sb = (sb_raw + 1023u) & ~1023u;
    char* smp = dsm + (sb - sb_raw);

    constexpr uint32_t OFF_B = 65536, BBUF = 16384, OFF_UPS = 98304;

    const int bm = blockIdx.x, b = bm >> 5;
    const int n0 = blockIdx.y;
    const int tid = threadIdx.x;
    const int wid = tid >> 5, lane = tid & 31;
    const int wm = (wid >> 2) * 64, wn = (wid & 3) * 32;

    const int row = tid >> 1, seg = tid & 1;
    const uint32_t rowoff = (uint32_t)(row * 128 + seg * 64);

    const __half* vrow = vp16 + (size_t)(b * 128 + row) * 256 + seg * 32;
    const __half* wrow = wp + (size_t)(n0 * 128 + row) * 256 + seg * 32;

    // ---- progressive prologue: g0=(A0,B0), g1=(A1,B1), g2=(A2), g3=(A3) ----
#pragma unroll
    for (int j = 0; j < 4; j++) {
        uint32_t sw = SWZ(rowoff + j * 16);
        cp16(sb + sw, vrow + j * 8);
        cp16(sb + OFF_B + sw, wrow + j * 8);
    }
    cp_commit();
#pragma unroll
    for (int j = 0; j < 4; j++) {
        uint32_t sw = SWZ(rowoff + j * 16);
        cp16(sb + 16384 + sw, vrow + 64 + j * 8);
        cp16(sb + OFF_B + BBUF + sw, wrow + 64 + j * 8);
    }
    cp_commit();
#pragma unroll
    for (int j = 0; j < 4; j++)
        cp16(sb + 32768 + SWZ(rowoff + j * 16), vrow + 128 + j * 8);
    cp_commit();
#pragma unroll
    for (int j = 0; j < 4; j++)
        cp16(sb + 49152 + SWZ(rowoff + j * 16), vrow + 192 + j * 8);
    cp_commit();

    // ---- up16[bm] -> smem (128 half2) ----
    __half2* ups2 = (__half2*)(smp + OFF_UPS);
    if (tid < 128) ups2[tid] = ((const __half2*)(up16 + (size_t)bm * 256))[tid];

    cp_wait<3>();      // g0 done: A0 + B0
    __syncthreads();   // + ups2 visible

    // ---- hoisted row bases and their swizzle bits (kept SEPARATE) ----
    uint32_t ra[4], sa[4], rb[2], sbz[2];
#pragma unroll
    for (int mi = 0; mi < 4; mi++) {
        ra[mi] = (uint32_t)((wm + mi * 16 + (lane & 15)) * 128);
        sa[mi] = (ra[mi] >> 3) & 0x70;
    }
#pragma unroll
    for (int np = 0; np < 2; np++) {
        rb[np] = (uint32_t)((wn + np * 16 + (lane & 15)) * 128);
        sbz[np] = (rb[np] >> 3) & 0x70;
    }
    const uint32_t acl = (uint32_t)((lane >> 4) * 16);
    const int lq = lane & 3;

    float c[4][4][4];
#pragma unroll
    for (int i = 0; i < 4; i++)
#pragma unroll
        for (int j = 0; j < 4; j++)
#pragma unroll
            for (int q = 0; q < 4; q++) c[i][j][q] = 0.f;

#pragma unroll
    for (int kc = 0; kc < 4; kc++) {
        uint32_t abase = sb + (uint32_t)kc * 16384;
        uint32_t bbase = sb + OFF_B + (uint32_t)(kc & 1) * BBUF;
#pragma unroll
        for (int ks = 0; ks < 4; ks++) {
            const int ksg = kc * 4 + ks;
            const __half2 mul0 = ups2[ksg * 8 + lq];
            const __half2 mul1 = ups2[ksg * 8 + 4 + lq];
            const uint32_t acol = (uint32_t)(ks * 32) + acl;
            uint32_t a[4][4], bm0[2][4], bfr[4][2];
            // B LDSM first: longest dependency chain (LDSM -> HMUL -> MMA)
#pragma unroll
            for (int np = 0; np < 2; np++)
                ldsm4(bm0[np][0], bm0[np][1], bm0[np][2], bm0[np][3],
                      bbase + rb[np] + (acol ^ sbz[np]));
#pragma unroll
            for (int mi = 0; mi < 4; mi++)
                ldsm4(a[mi][0], a[mi][1], a[mi][2], a[mi][3],
                      abase + ra[mi] + (acol ^ sa[mi]));
#pragma unroll
            for (int np = 0; np < 2; np++) {
                bfr[2 * np][0]     = hmul2u(bm0[np][0], mul0);
                bfr[2 * np][1]     = hmul2u(bm0[np][2], mul1);
                bfr[2 * np + 1][0] = hmul2u(bm0[np][1], mul0);
                bfr[2 * np + 1][1] = hmul2u(bm0[np][3], mul1);
            }
#pragma unroll
            for (int mi = 0; mi < 4; mi++)
#pragma unroll
                for (int nj = 0; nj < 4; nj++)
                    mma_f16(c[mi][nj], a[mi], bfr[nj]);
        }
        // pipeline control
        if (kc == 0) {
            __syncthreads();                       // all warps done with B buf0
#pragma unroll
            for (int j = 0; j < 4; j++)            // B2 -> buf0 (g4)
                cp16(sb + OFF_B + SWZ(rowoff + j * 16), wrow + 128 + j * 8);
            cp_commit();
            cp_wait<3>();                          // g1 done (A1 + B1)
            __syncthreads();
        } else if (kc == 1) {
            __syncthreads();                       // done with B buf1
#pragma unroll
            for (int j = 0; j < 4; j++)            // B3 -> buf1 (g5)
                cp16(sb + OFF_B + BBUF + SWZ(rowoff + j * 16), wrow + 192 + j * 8);
            cp_commit();
            cp_wait<1>();                          // g2,g3,g4 done (A2,A3,B2)
            __syncthreads();
        } else if (kc == 2) {
            cp_wait<0>();                          // g5 done (B3)
            __syncthreads();
        }
    }

    // ---- epilogue: +bias, relu, store ----
    const int rin = lane >> 2, cin = (lane & 3) * 2;
    float* obase = out + (size_t)bm * 128 * 256 + n0 * 128;
#pragma unroll
    for (int nj = 0; nj < 4; nj++) {
        const int f = wn + nj * 8 + cin;
        const float b0 = bp[n0 * 128 + f], b1 = bp[n0 * 128 + f + 1];
#pragma unroll
        for (int mi = 0; mi < 4; mi++) {
            float* p0 = obase + (size_t)(wm + mi * 16 + rin) * 256 + f;
            *(float2*)p0 = make_float2(fmaxf(c[mi][nj][0] + b0, 0.f),
                                       fmaxf(c[mi][nj][1] + b1, 0.f));
            *(float2*)(p0 + 8 * 256) = make_float2(fmaxf(c[mi][nj][2] + b0, 0.f),
                                                   fmaxf(c[mi][nj][3] + b1, 0.f));
        }
    }
}

// -------------------- host launch -------------------------------------------
extern "C" void kernel_launch(void* const* d_in, const int* in_sizes, int n_in,
                              void* d_out, int out_size) {
    const float* u  = (const float*)d_in[0];   // (32,32,1024)
    const float* v  = (const float*)d_in[1];   // (32,128,2048)
    const float* Wu = (const float*)d_in[2];   // (256,1024)
    const float* Wv = (const float*)d_in[3];   // (256,2048)
    const float* Wp = (const float*)d_in[4];   // (256,256)
    const float* bp = (const float*)d_in[5];   // (256,)
    float* out = (float*)d_out;                // (32,32,128,256)

    float* vpp_p;
    __half *up16, *vp16, *wu, *wv, *wp;
    cudaGetSymbolAddress((void**)&vpp_p, g_vp_part);
    cudaGetSymbolAddress((void**)&up16, g_up16);
    cudaGetSymbolAddress((void**)&vp16, g_vp16);
    cudaGetSymbolAddress((void**)&wu, g_wu16);
    cudaGetSymbolAddress((void**)&wv, g_wv16);
    cudaGetSymbolAddress((void**)&wp, g_wp16);

    const int PROJ_SMEM = 2 * 32768 + 1024;          // 66560
    const int FUSE_SMEM = 98304 + 512 + 1024;        // 99840
    cudaFuncSetAttribute(proj_mma, cudaFuncAttributeMaxDynamicSharedMemorySize, PROJ_SMEM);
    cudaFuncSetAttribute(fuse_mma, cudaFuncAttributeMaxDynamicSharedMemorySize, FUSE_SMEM);

    const int wtotal = 256 * 1024 + 256 * 2048 + 256 * 256;
    prep_cvt<<<(wtotal / 4 + 255) / 256, 256>>>(Wu, Wv, Wp, wu, wv, wp);
    proj_mma<<<144, 256, PROJ_SMEM>>>(u, v, wu, wv, up16, vpp_p);
    add_parts<<<1024, 256>>>(vpp_p, vp16);
    fuse_mma<<<dim3(1024, 2), 256, FUSE_SMEM>>>(up16, vp16, wp, bp, out);
}

// round 15
// speedup vs baseline: 1.5793x; 1.5793x over previous
#include <cuda_runtime.h>
#include <cuda_fp16.h>
#include <cstdint>

// ============================================================================
// LowRankBilinearFusion, HMMA fp16 (R13 + full-chip proj):
//   prep: u,v,Wu,Wv,Wp -> fp16
//   proj: up_part = u@Wu^T k-split x2; vp_part = v@Wv^T k-split x4 (fp32),
//         K=512/CTA, 288 CTAs = one full wave at 2 CTAs/SM.
//   add:  vp16 = fp16(sum4), up16 = fp16(sum2)
//   fuse: out[bm,n0] = relu(vp16[b] @ (up16[bm] ⊙ Wp16[n0])^T + bp)
//     (verbatim R13: 256 thr, 2x4 warps, 64x32 tiles, resident A,
//      B-fragment scaling, add/xor-correct hoisted addressing, 2 CTAs/SM)
// ============================================================================

__device__ float  g_vp_part[4 * 4096 * 256];
__device__ float  g_up_part[2 * 1024 * 256];
__device__ __half g_up16[1024 * 256];
__device__ __half g_vp16[4096 * 256];
__device__ __half g_u16[1024 * 1024];
__device__ __half g_v16[4096 * 2048];
__device__ __half g_wu16[256 * 1024];
__device__ __half g_wv16[256 * 2048];
__device__ __half g_wp16[256 * 256];

#define SWZ(o) ((o) ^ (((o) >> 3) & 0x70))

__device__ __forceinline__ uint32_t smem_u32(const void* p) {
    uint32_t a;
    asm("{ .reg .u64 t; cvta.to.shared.u64 t, %1; cvt.u32.u64 %0, t; }" : "=r"(a) : "l"(p));
    return a;
}
__device__ __forceinline__ void ldsm4(uint32_t& r0, uint32_t& r1, uint32_t& r2, uint32_t& r3,
                                      uint32_t addr) {
    asm volatile("ldmatrix.sync.aligned.m8n8.x4.shared.b16 {%0,%1,%2,%3}, [%4];"
                 : "=r"(r0), "=r"(r1), "=r"(r2), "=r"(r3) : "r"(addr));
}
__device__ __forceinline__ void mma_f16(float* c, const uint32_t* a, const uint32_t* b) {
    asm volatile(
        "mma.sync.aligned.m16n8k16.row.col.f32.f16.f16.f32 "
        "{%0,%1,%2,%3}, {%4,%5,%6,%7}, {%8,%9}, {%0,%1,%2,%3};"
        : "+f"(c[0]), "+f"(c[1]), "+f"(c[2]), "+f"(c[3])
        : "r"(a[0]), "r"(a[1]), "r"(a[2]), "r"(a[3]), "r"(b[0]), "r"(b[1]));
}
__device__ __forceinline__ void cp16(uint32_t dst, const void* src) {
    asm volatile("cp.async.cg.shared.global [%0], [%1], 16;" :: "r"(dst), "l"(src));
}
__device__ __forceinline__ void cp_commit() { asm volatile("cp.async.commit_group;" ::: "memory"); }
template <int N>
__device__ __forceinline__ void cp_wait() { asm volatile("cp.async.wait_group %0;" :: "n"(N) : "memory"); }
__device__ __forceinline__ uint32_t hmul2u(uint32_t a, __half2 m) {
    __half2 r = __hmul2(*(__half2*)&a, m);
    return *(uint32_t*)&r;
}
__device__ __forceinline__ uint32_t packh2(float a, float b) {
    __half2 h = __floats2half2_rn(a, b);
    return *(uint32_t*)&h;
}

// -------------------- prep: convert all operands to fp16 ---------------------
__global__ void __launch_bounds__(256) prep_cvt(
    const float* __restrict__ u, const float* __restrict__ v,
    const float* __restrict__ Wu, const float* __restrict__ Wv, const float* __restrict__ Wp,
    __half* u16, __half* v16, __half* wu, __half* wv, __half* wp)
{
    const int N1 = 1024 * 1024, N2 = 4096 * 2048;
    const int N3 = 256 * 1024, N4 = 256 * 2048, N5 = 256 * 256;
    int t = blockIdx.x * 256 + threadIdx.x;
    size_t i = (size_t)t * 4;
    const float* src; __half* dst; size_t j;
    if (i < N1)                          { src = u;  dst = u16; j = i; }
    else if (i < (size_t)N1 + N2)        { src = v;  dst = v16; j = i - N1; }
    else if (i < (size_t)N1 + N2 + N3)   { src = Wu; dst = wu;  j = i - N1 - N2; }
    else if (i < (size_t)N1 + N2 + N3 + N4) { src = Wv; dst = wv; j = i - N1 - N2 - N3; }
    else if (i < (size_t)N1 + N2 + N3 + N4 + N5) { src = Wp; dst = wp; j = i - N1 - N2 - N3 - N4; }
    else return;
    float4 x = *(const float4*)(src + j);
    uint2 o; o.x = packh2(x.x, x.y); o.y = packh2(x.z, x.w);
    *(uint2*)(dst + j) = o;
}

// ============================================================================
// proj: C[128x128] = A16 @ B16^T, K = 512 per CTA (8 chunks of 64).
// Grid: 0..31 up (mt8 x n2 x kh2) -> fp32 partials;
//       32..287 vp (mt32 x n2 x kh4) -> fp32 partials.
// 256 thr, 8 warps 2x4, warp tile 64x32. 2 CTAs/SM; 288 CTAs = full wave.
// ============================================================================
__global__ void __launch_bounds__(256, 2) proj_mma(
    const __half* __restrict__ u16, const __half* __restrict__ v16,
    const __half* __restrict__ wu, const __half* __restrict__ wv,
    float* __restrict__ up_part, float* __restrict__ vp_part)
{
    extern __shared__ char dsm[];
    uint32_t sb_raw = smem_u32(dsm);
    uint32_t sb = (sb_raw + 1023u) & ~1023u;

    constexpr uint32_t BUF = 32768, OFF_B = 16384;

    const int bid = blockIdx.x;
    const int tid = threadIdx.x;
    const int wid = tid >> 5, lane = tid & 31;
    const int wm = (wid >> 2) * 64, wn = (wid & 3) * 32;

    const __half *A, *B;
    int lda, ldb;
    float* Cf;
    if (bid < 32) {
        int mt = bid >> 2, n0 = (bid >> 1) & 1, kh = bid & 1;
        A = u16 + (size_t)mt * 128 * 1024 + kh * 512; lda = 1024;
        B = wu + (size_t)n0 * 128 * 1024 + kh * 512; ldb = 1024;
        Cf = up_part + (size_t)kh * 1024 * 256 + (size_t)mt * 128 * 256 + n0 * 128;
    } else {
        int b2 = bid - 32;
        int mt = b2 >> 3, n0 = (b2 >> 2) & 1, kh = b2 & 3;
        A = v16 + (size_t)mt * 128 * 2048 + kh * 512; lda = 2048;
        B = wv + (size_t)n0 * 128 * 2048 + kh * 512; ldb = 2048;
        Cf = vp_part + (size_t)kh * 4096 * 256 + (size_t)mt * 128 * 256 + n0 * 128;
    }

    const int row = tid >> 1, seg = tid & 1;
    const __half* pA = A + (size_t)row * lda + seg * 32;
    const __half* pB = B + (size_t)row * ldb + seg * 32;
    const uint32_t rowoff = (uint32_t)(row * 128 + seg * 64);

    float c[4][4][4];
#pragma unroll
    for (int i = 0; i < 4; i++)
#pragma unroll
        for (int j = 0; j < 4; j++)
#pragma unroll
            for (int q = 0; q < 4; q++) c[i][j][q] = 0.f;

    auto issue = [&](int kc, int bf) {
        uint32_t base = sb + (uint32_t)bf * BUF;
#pragma unroll
        for (int j = 0; j < 4; j++) {
            uint32_t sw = SWZ(rowoff + j * 16);
            cp16(base + sw,         pA + kc * 64 + j * 8);
            cp16(base + OFF_B + sw, pB + kc * 64 + j * 8);
        }
    };
    auto mmas = [&](int bf) {
        uint32_t base = sb + (uint32_t)bf * BUF;
#pragma unroll
        for (int ks = 0; ks < 4; ks++) {
            uint32_t a[4][4], bfr[4][2];
            const uint32_t acol = (uint32_t)(ks * 32 + (lane >> 4) * 16);
#pragma unroll
            for (int mi = 0; mi < 4; mi++) {
                uint32_t ro = (uint32_t)((wm + mi * 16 + (lane & 15)) * 128) + acol;
                ldsm4(a[mi][0], a[mi][1], a[mi][2], a[mi][3], base + SWZ(ro));
            }
#pragma unroll
            for (int np = 0; np < 2; np++) {
                uint32_t ro = (uint32_t)((wn + np * 16 + (lane & 15)) * 128) + acol;
                uint32_t m0, m1, m2, m3;
                ldsm4(m0, m1, m2, m3, base + OFF_B + SWZ(ro));
                bfr[2 * np][0] = m0; bfr[2 * np][1] = m2;
                bfr[2 * np + 1][0] = m1; bfr[2 * np + 1][1] = m3;
            }
#pragma unroll
            for (int mi = 0; mi < 4; mi++)
#pragma unroll
                for (int nj = 0; nj < 4; nj++)
                    mma_f16(c[mi][nj], a[mi], bfr[nj]);
        }
    };

    issue(0, 0); cp_commit();
    for (int kc = 0; kc < 8; kc++) {
        if (kc < 7) { issue(kc + 1, (kc + 1) & 1); cp_commit(); cp_wait<1>(); }
        else cp_wait<0>();
        __syncthreads();
        mmas(kc & 1);
        __syncthreads();
    }

    const int rin = lane >> 2, cin = (lane & 3) * 2;
#pragma unroll
    for (int mi = 0; mi < 4; mi++)
#pragma unroll
        for (int nj = 0; nj < 4; nj++) {
            float* p0 = Cf + (size_t)(wm + mi * 16 + rin) * 256 + wn + nj * 8 + cin;
            *(float2*)p0 = make_float2(c[mi][nj][0], c[mi][nj][1]);
            *(float2*)(p0 + 8 * 256) = make_float2(c[mi][nj][2], c[mi][nj][3]);
        }
}

// -------------------- add: vp16 = fp16(sum4), up16 = fp16(sum2) --------------
__global__ void __launch_bounds__(256) add_parts(
    const float* __restrict__ vpp, const float* __restrict__ upp,
    __half* __restrict__ vp16, __half* __restrict__ up16)
{
    const int NV4 = 4096 * 256 / 4;   // 262144 vp slots
    const int NU4 = 1024 * 256 / 4;   // 65536 up slots
    int idx = blockIdx.x * 256 + threadIdx.x;
    if (idx < NV4) {
        size_t i = (size_t)idx * 4;
        float4 a = *(const float4*)(vpp + i);
        float4 b = *(const float4*)(vpp + (size_t)4096 * 256 + i);
        float4 d = *(const float4*)(vpp + (size_t)2 * 4096 * 256 + i);
        float4 e = *(const float4*)(vpp + (size_t)3 * 4096 * 256 + i);
        uint2 o;
        o.x = packh2(a.x + b.x + d.x + e.x, a.y + b.y + d.y + e.y);
        o.y = packh2(a.z + b.z + d.z + e.z, a.w + b.w + d.w + e.w);
        *(uint2*)(vp16 + i) = o;
    } else if (idx < NV4 + NU4) {
        size_t i = (size_t)(idx - NV4) * 4;
        float4 a = *(const float4*)(upp + i);
        float4 b = *(const float4*)(upp + (size_t)1024 * 256 + i);
        uint2 o;
        o.x = packh2(a.x + b.x, a.y + b.y);
        o.y = packh2(a.z + b.z, a.w + b.w);
        *(uint2*)(up16 + i) = o;
    }
}

// ============================================================================
// fuse: out[bm, n0] = relu(vp16[b] @ (up16[bm] ⊙ Wp16[n0])^T + bp)
// 128 x 128 per CTA, K=256. 256 threads, 8 warps (2x4), warp tile 64x32.
// A = raw vp16 resident, progressive groups (A0,B0),(A1,B1),(A2),(A3).
// up16 applied to B fragments. addr = base + ra + (acol ^ sz). 2 CTAs/SM.
// (verbatim R13)
// ============================================================================
__global__ void __launch_bounds__(256, 2) fuse_mma(
    const __half* __restrict__ up16, const __half* __restrict__ vp16,
    const __half* __restrict__ wp, const float* __restrict__ bp,
    float* __restrict__ out)
{
    extern __shared__ char dsm[];
    uint32_t sb_raw = smem_u32(dsm);
    uint32_t sb = (sb_raw + 1023u) & ~1023u;
    char* smp = dsm + (sb - sb_raw);

    constexpr uint32_t OFF_B = 65536, BBUF = 16384, OFF_UPS = 98304;

    const int bm = blockIdx.x, b = bm >> 5;
    const int n0 = blockIdx.y;
    const int tid = threadIdx.x;
    const int wid = tid >> 5, lane = tid & 31;
    const int wm = (wid >> 2) * 64, wn = (wid & 3) * 32;

    const int row = tid >> 1, seg = tid & 1;
    const uint32_t rowoff = (uint32_t)(row * 128 + seg * 64);

    const __half* vrow = vp16 + (size_t)(b * 128 + row) * 256 + seg * 32;
    const __half* wrow = wp + (size_t)(n0 * 128 + row) * 256 + seg * 32;

    // ---- progressive prologue: g0=(A0,B0), g1=(A1,B1), g2=(A2), g3=(A3) ----
#pragma unroll
    for (int j = 0; j < 4; j++) {
        uint32_t sw = SWZ(rowoff + j * 16);
        cp16(sb + sw, vrow + j * 8);
        cp16(sb + OFF_B + sw, wrow + j * 8);
    }
    cp_commit();
#pragma unroll
    for (int j = 0; j < 4; j++) {
        uint32_t sw = SWZ(rowoff + j * 16);
        cp16(sb + 16384 + sw, vrow + 64 + j * 8);
        cp16(sb + OFF_B + BBUF + sw, wrow + 64 + j * 8);
    }
    cp_commit();
#pragma unroll
    for (int j = 0; j < 4; j++)
        cp16(sb + 32768 + SWZ(rowoff + j * 16), vrow + 128 + j * 8);
    cp_commit();
#pragma unroll
    for (int j = 0; j < 4; j++)
        cp16(sb + 49152 + SWZ(rowoff + j * 16), vrow + 192 + j * 8);
    cp_commit();

    // ---- up16[bm] -> smem (128 half2) ----
    __half2* ups2 = (__half2*)(smp + OFF_UPS);
    if (tid < 128) ups2[tid] = ((const __half2*)(up16 + (size_t)bm * 256))[tid];

    cp_wait<3>();      // g0 done: A0 + B0
    __syncthreads();   // + ups2 visible

    // ---- hoisted row bases and their swizzle bits (kept SEPARATE) ----
    uint32_t ra[4], sa[4], rb[2], sbz[2];
#pragma unroll
    for (int mi = 0; mi < 4; mi++) {
        ra[mi] = (uint32_t)((wm + mi * 16 + (lane & 15)) * 128);
        sa[mi] = (ra[mi] >> 3) & 0x70;
    }
#pragma unroll
    for (int np = 0; np < 2; np++) {
        rb[np] = (uint32_t)((wn + np * 16 + (lane & 15)) * 128);
        sbz[np] = (rb[np] >> 3) & 0x70;
    }
    const uint32_t acl = (uint32_t)((lane >> 4) * 16);
    const int lq = lane & 3;

    float c[4][4][4];
#pragma unroll
    for (int i = 0; i < 4; i++)
#pragma unroll
        for (int j = 0; j < 4; j++)
#pragma unroll
            for (int q = 0; q < 4; q++) c[i][j][q] = 0.f;

#pragma unroll
    for (int kc = 0; kc < 4; kc++) {
        uint32_t abase = sb + (uint32_t)kc * 16384;
        uint32_t bbase = sb + OFF_B + (uint32_t)(kc & 1) * BBUF;
#pragma unroll
        for (int ks = 0; ks < 4; ks++) {
            const int ksg = kc * 4 + ks;
            const __half2 mul0 = ups2[ksg * 8 + lq];
            const __half2 mul1 = ups2[ksg * 8 + 4 + lq];
            const uint32_t acol = (uint32_t)(ks * 32) + acl;
            uint32_t a[4][4], bfr[4][2];
#pragma unroll
            for (int mi = 0; mi < 4; mi++)
                ldsm4(a[mi][0], a[mi][1], a[mi][2], a[mi][3],
                      abase + ra[mi] + (acol ^ sa[mi]));
#pragma unroll
            for (int np = 0; np < 2; np++) {
                uint32_t m0, m1, m2, m3;
                ldsm4(m0, m1, m2, m3, bbase + rb[np] + (acol ^ sbz[np]));
                bfr[2 * np][0]     = hmul2u(m0, mul0);
                bfr[2 * np][1]     = hmul2u(m2, mul1);
                bfr[2 * np + 1][0] = hmul2u(m1, mul0);
                bfr[2 * np + 1][1] = hmul2u(m3, mul1);
            }
#pragma unroll
            for (int mi = 0; mi < 4; mi++)
#pragma unroll
                for (int nj = 0; nj < 4; nj++)
                    mma_f16(c[mi][nj], a[mi], bfr[nj]);
        }
        // pipeline control
        if (kc == 0) {
            __syncthreads();                       // all warps done with B buf0
#pragma unroll
            for (int j = 0; j < 4; j++)            // B2 -> buf0 (g4)
                cp16(sb + OFF_B + SWZ(rowoff + j * 16), wrow + 128 + j * 8);
            cp_commit();
            cp_wait<3>();                          // g1 done (A1 + B1)
            __syncthreads();
        } else if (kc == 1) {
            __syncthreads();                       // done with B buf1
#pragma unroll
            for (int j = 0; j < 4; j++)            // B3 -> buf1 (g5)
                cp16(sb + OFF_B + BBUF + SWZ(rowoff + j * 16), wrow + 192 + j * 8);
            cp_commit();
            cp_wait<1>();                          // g2,g3,g4 done (A2,A3,B2)
            __syncthreads();
        } else if (kc == 2) {
            cp_wait<0>();                          // g5 done (B3)
            __syncthreads();
        }
    }

    // ---- epilogue: +bias, relu, store ----
    const int rin = lane >> 2, cin = (lane & 3) * 2;
    float* obase = out + (size_t)bm * 128 * 256 + n0 * 128;
#pragma unroll
    for (int nj = 0; nj < 4; nj++) {
        const int f = wn + nj * 8 + cin;
        const float b0 = bp[n0 * 128 + f], b1 = bp[n0 * 128 + f + 1];
#pragma unroll
        for (int mi = 0; mi < 4; mi++) {
            float* p0 = obase + (size_t)(wm + mi * 16 + rin) * 256 + f;
            *(float2*)p0 = make_float2(fmaxf(c[mi][nj][0] + b0, 0.f),
                                       fmaxf(c[mi][nj][1] + b1, 0.f));
            *(float2*)(p0 + 8 * 256) = make_float2(fmaxf(c[mi][nj][2] + b0, 0.f),
                                                   fmaxf(c[mi][nj][3] + b1, 0.f));
        }
    }
}

// -------------------- host launch -------------------------------------------
extern "C" void kernel_launch(void* const* d_in, const int* in_sizes, int n_in,
                              void* d_out, int out_size) {
    const float* u  = (const float*)d_in[0];   // (32,32,1024)
    const float* v  = (const float*)d_in[1];   // (32,128,2048)
    const float* Wu = (const float*)d_in[2];   // (256,1024)
    const float* Wv = (const float*)d_in[3];   // (256,2048)
    const float* Wp = (const float*)d_in[4];   // (256,256)
    const float* bp = (const float*)d_in[5];   // (256,)
    float* out = (float*)d_out;                // (32,32,128,256)

    float *vpp_p, *upp_p;
    __half *up16, *vp16, *u16, *v16, *wu, *wv, *wp;
    cudaGetSymbolAddress((void**)&vpp_p, g_vp_part);
    cudaGetSymbolAddress((void**)&upp_p, g_up_part);
    cudaGetSymbolAddress((void**)&up16, g_up16);
    cudaGetSymbolAddress((void**)&vp16, g_vp16);
    cudaGetSymbolAddress((void**)&u16, g_u16);
    cudaGetSymbolAddress((void**)&v16, g_v16);
    cudaGetSymbolAddress((void**)&wu, g_wu16);
    cudaGetSymbolAddress((void**)&wv, g_wv16);
    cudaGetSymbolAddress((void**)&wp, g_wp16);

    const int PROJ_SMEM = 2 * 32768 + 1024;          // 66560
    const int FUSE_SMEM = 98304 + 512 + 1024;        // 99840
    cudaFuncSetAttribute(proj_mma, cudaFuncAttributeMaxDynamicSharedMemorySize, PROJ_SMEM);
    cudaFuncSetAttribute(fuse_mma, cudaFuncAttributeMaxDynamicSharedMemorySize, FUSE_SMEM);

    const int total = 1024 * 1024 + 4096 * 2048 + 256 * 1024 + 256 * 2048 + 256 * 256;
    prep_cvt<<<(total / 4 + 255) / 256, 256>>>(u, v, Wu, Wv, Wp, u16, v16, wu, wv, wp);
    proj_mma<<<288, 256, PROJ_SMEM>>>(u16, v16, wu, wv, upp_p, vpp_p);
    add_parts<<<1280, 256>>>(vpp_p, upp_p, vp16, up16);
    fuse_mma<<<dim3(1024, 2), 256, FUSE_SMEM>>>(up16, vp16, wp, bp, out);
}

// round 16
// speedup vs baseline: 1.5865x; 1.0045x over previous
#include <cuda_runtime.h>
#include <cuda_fp16.h>
#include <cstdint>

// ============================================================================
// LowRankBilinearFusion, HMMA fp16:
//   prep: u,v,Wu,Wv,Wp -> fp16
//   proj: up_part = u@Wu^T k-split x2; vp_part = v@Wv^T k-split x4 (fp32),
//         K=512/CTA, 288 CTAs = one full wave at 2 CTAs/SM.
//   add:  vp16 = fp16(sum4), up16 = fp16(sum2)
//   fuse: out[bm] = relu(vp16[b] @ (up16[bm] ⊙ Wp16)^T + bp)
//     1024 CTAs; each CTA processes BOTH n-halves sequentially, reusing the
//     resident 64KB A tile (loads A once instead of twice). Half-0 epilogue
//     overlaps half-1's B prologue. 256 thr, 2x4 warps, 64x32 tiles,
//     B-fragment scaling, hoisted add/xor-correct addressing, 2 CTAs/SM.
// ============================================================================

__device__ float  g_vp_part[4 * 4096 * 256];
__device__ float  g_up_part[2 * 1024 * 256];
__device__ __half g_up16[1024 * 256];
__device__ __half g_vp16[4096 * 256];
__device__ __half g_u16[1024 * 1024];
__device__ __half g_v16[4096 * 2048];
__device__ __half g_wu16[256 * 1024];
__device__ __half g_wv16[256 * 2048];
__device__ __half g_wp16[256 * 256];

#define SWZ(o) ((o) ^ (((o) >> 3) & 0x70))

__device__ __forceinline__ uint32_t smem_u32(const void* p) {
    uint32_t a;
    asm("{ .reg .u64 t; cvta.to.shared.u64 t, %1; cvt.u32.u64 %0, t; }" : "=r"(a) : "l"(p));
    return a;
}
__device__ __forceinline__ void ldsm4(uint32_t& r0, uint32_t& r1, uint32_t& r2, uint32_t& r3,
                                      uint32_t addr) {
    asm volatile("ldmatrix.sync.aligned.m8n8.x4.shared.b16 {%0,%1,%2,%3}, [%4];"
                 : "=r"(r0), "=r"(r1), "=r"(r2), "=r"(r3) : "r"(addr));
}
__device__ __forceinline__ void mma_f16(float* c, const uint32_t* a, const uint32_t* b) {
    asm volatile(
        "mma.sync.aligned.m16n8k16.row.col.f32.f16.f16.f32 "
        "{%0,%1,%2,%3}, {%4,%5,%6,%7}, {%8,%9}, {%0,%1,%2,%3};"
        : "+f"(c[0]), "+f"(c[1]), "+f"(c[2]), "+f"(c[3])
        : "r"(a[0]), "r"(a[1]), "r"(a[2]), "r"(a[3]), "r"(b[0]), "r"(b[1]));
}
__device__ __forceinline__ void cp16(uint32_t dst, const void* src) {
    asm volatile("cp.async.cg.shared.global [%0], [%1], 16;" :: "r"(dst), "l"(src));
}
__device__ __forceinline__ void cp_commit() { asm volatile("cp.async.commit_group;" ::: "memory"); }
template <int N>
__device__ __forceinline__ void cp_wait() { asm volatile("cp.async.wait_group %0;" :: "n"(N) : "memory"); }
__device__ __forceinline__ uint32_t hmul2u(uint32_t a, __half2 m) {
    __half2 r = __hmul2(*(__half2*)&a, m);
    return *(uint32_t*)&r;
}
__device__ __forceinline__ uint32_t packh2(float a, float b) {
    __half2 h = __floats2half2_rn(a, b);
    return *(uint32_t*)&h;
}

// -------------------- prep: convert all operands to fp16 ---------------------
__global__ void __launch_bounds__(256) prep_cvt(
    const float* __restrict__ u, const float* __restrict__ v,
    const float* __restrict__ Wu, const float* __restrict__ Wv, const float* __restrict__ Wp,
    __half* u16, __half* v16, __half* wu, __half* wv, __half* wp)
{
    const int N1 = 1024 * 1024, N2 = 4096 * 2048;
    const int N3 = 256 * 1024, N4 = 256 * 2048, N5 = 256 * 256;
    int t = blockIdx.x * 256 + threadIdx.x;
    size_t i = (size_t)t * 4;
    const float* src; __half* dst; size_t j;
    if (i < N1)                          { src = u;  dst = u16; j = i; }
    else if (i < (size_t)N1 + N2)        { src = v;  dst = v16; j = i - N1; }
    else if (i < (size_t)N1 + N2 + N3)   { src = Wu; dst = wu;  j = i - N1 - N2; }
    else if (i < (size_t)N1 + N2 + N3 + N4) { src = Wv; dst = wv; j = i - N1 - N2 - N3; }
    else if (i < (size_t)N1 + N2 + N3 + N4 + N5) { src = Wp; dst = wp; j = i - N1 - N2 - N3 - N4; }
    else return;
    float4 x = *(const float4*)(src + j);
    uint2 o; o.x = packh2(x.x, x.y); o.y = packh2(x.z, x.w);
    *(uint2*)(dst + j) = o;
}

// ============================================================================
// proj: C[128x128] = A16 @ B16^T, K = 512 per CTA (8 chunks of 64).
// Grid: 0..31 up (mt8 x n2 x kh2); 32..287 vp (mt32 x n2 x kh4). fp32 partials.
// 256 thr, 8 warps 2x4, warp tile 64x32. 2 CTAs/SM; 288 CTAs = full wave.
// ============================================================================
__global__ void __launch_bounds__(256, 2) proj_mma(
    const __half* __restrict__ u16, const __half* __restrict__ v16,
    const __half* __restrict__ wu, const __half* __restrict__ wv,
    float* __restrict__ up_part, float* __restrict__ vp_part)
{
    extern __shared__ char dsm[];
    uint32_t sb_raw = smem_u32(dsm);
    uint32_t sb = (sb_raw + 1023u) & ~1023u;

    constexpr uint32_t BUF = 32768, OFF_B = 16384;

    const int bid = blockIdx.x;
    const int tid = threadIdx.x;
    const int wid = tid >> 5, lane = tid & 31;
    const int wm = (wid >> 2) * 64, wn = (wid & 3) * 32;

    const __half *A, *B;
    int lda, ldb;
    float* Cf;
    if (bid < 32) {
        int mt = bid >> 2, n0 = (bid >> 1) & 1, kh = bid & 1;
        A = u16 + (size_t)mt * 128 * 1024 + kh * 512; lda = 1024;
        B = wu + (size_t)n0 * 128 * 1024 + kh * 512; ldb = 1024;
        Cf = up_part + (size_t)kh * 1024 * 256 + (size_t)mt * 128 * 256 + n0 * 128;
    } else {
        int b2 = bid - 32;
        int mt = b2 >> 3, n0 = (b2 >> 2) & 1, kh = b2 & 3;
        A = v16 + (size_t)mt * 128 * 2048 + kh * 512; lda = 2048;
        B = wv + (size_t)n0 * 128 * 2048 + kh * 512; ldb = 2048;
        Cf = vp_part + (size_t)kh * 4096 * 256 + (size_t)mt * 128 * 256 + n0 * 128;
    }

    const int row = tid >> 1, seg = tid & 1;
    const __half* pA = A + (size_t)row * lda + seg * 32;
    const __half* pB = B + (size_t)row * ldb + seg * 32;
    const uint32_t rowoff = (uint32_t)(row * 128 + seg * 64);

    float c[4][4][4];
#pragma unroll
    for (int i = 0; i < 4; i++)
#pragma unroll
        for (int j = 0; j < 4; j++)
#pragma unroll
            for (int q = 0; q < 4; q++) c[i][j][q] = 0.f;

    auto issue = [&](int kc, int bf) {
        uint32_t base = sb + (uint32_t)bf * BUF;
#pragma unroll
        for (int j = 0; j < 4; j++) {
            uint32_t sw = SWZ(rowoff + j * 16);
            cp16(base + sw,         pA + kc * 64 + j * 8);
            cp16(base + OFF_B + sw, pB + kc * 64 + j * 8);
        }
    };
    auto mmas = [&](int bf) {
        uint32_t base = sb + (uint32_t)bf * BUF;
#pragma unroll
        for (int ks = 0; ks < 4; ks++) {
            uint32_t a[4][4], bfr[4][2];
            const uint32_t acol = (uint32_t)(ks * 32 + (lane >> 4) * 16);
#pragma unroll
            for (int mi = 0; mi < 4; mi++) {
                uint32_t ro = (uint32_t)((wm + mi * 16 + (lane & 15)) * 128) + acol;
                ldsm4(a[mi][0], a[mi][1], a[mi][2], a[mi][3], base + SWZ(ro));
            }
#pragma unroll
            for (int np = 0; np < 2; np++) {
                uint32_t ro = (uint32_t)((wn + np * 16 + (lane & 15)) * 128) + acol;
                uint32_t m0, m1, m2, m3;
                ldsm4(m0, m1, m2, m3, base + OFF_B + SWZ(ro));
                bfr[2 * np][0] = m0; bfr[2 * np][1] = m2;
                bfr[2 * np + 1][0] = m1; bfr[2 * np + 1][1] = m3;
            }
#pragma unroll
            for (int mi = 0; mi < 4; mi++)
#pragma unroll
                for (int nj = 0; nj < 4; nj++)
                    mma_f16(c[mi][nj], a[mi], bfr[nj]);
        }
    };

    issue(0, 0); cp_commit();
    for (int kc = 0; kc < 8; kc++) {
        if (kc < 7) { issue(kc + 1, (kc + 1) & 1); cp_commit(); cp_wait<1>(); }
        else cp_wait<0>();
        __syncthreads();
        mmas(kc & 1);
        __syncthreads();
    }

    const int rin = lane >> 2, cin = (lane & 3) * 2;
#pragma unroll
    for (int mi = 0; mi < 4; mi++)
#pragma unroll
        for (int nj = 0; nj < 4; nj++) {
            float* p0 = Cf + (size_t)(wm + mi * 16 + rin) * 256 + wn + nj * 8 + cin;
            *(float2*)p0 = make_float2(c[mi][nj][0], c[mi][nj][1]);
            *(float2*)(p0 + 8 * 256) = make_float2(c[mi][nj][2], c[mi][nj][3]);
        }
}

// -------------------- add: vp16 = fp16(sum4), up16 = fp16(sum2) --------------
__global__ void __launch_bounds__(256) add_parts(
    const float* __restrict__ vpp, const float* __restrict__ upp,
    __half* __restrict__ vp16, __half* __restrict__ up16)
{
    const int NV4 = 4096 * 256 / 4;
    const int NU4 = 1024 * 256 / 4;
    int idx = blockIdx.x * 256 + threadIdx.x;
    if (idx < NV4) {
        size_t i = (size_t)idx * 4;
        float4 a = *(const float4*)(vpp + i);
        float4 b = *(const float4*)(vpp + (size_t)4096 * 256 + i);
        float4 d = *(const float4*)(vpp + (size_t)2 * 4096 * 256 + i);
        float4 e = *(const float4*)(vpp + (size_t)3 * 4096 * 256 + i);
        uint2 o;
        o.x = packh2(a.x + b.x + d.x + e.x, a.y + b.y + d.y + e.y);
        o.y = packh2(a.z + b.z + d.z + e.z, a.w + b.w + d.w + e.w);
        *(uint2*)(vp16 + i) = o;
    } else if (idx < NV4 + NU4) {
        size_t i = (size_t)(idx - NV4) * 4;
        float4 a = *(const float4*)(upp + i);
        float4 b = *(const float4*)(upp + (size_t)1024 * 256 + i);
        uint2 o;
        o.x = packh2(a.x + b.x, a.y + b.y);
        o.y = packh2(a.z + b.z, a.w + b.w);
        *(uint2*)(up16 + i) = o;
    }
}

// ============================================================================
// fuse: out[bm] = relu(vp16[b] @ (up16[bm] ⊙ Wp16)^T + bp)
// 1024 CTAs; A (64KB) resident ONCE, two sequential n-halves share it.
// Per half: K=256 in 4 chunks, B double-buffered 2x16KB. Half-0 epilogue
// overlaps half-1 B prologue. 256 thr, 2x4 warps, 64x32 tiles. 2 CTAs/SM.
// ============================================================================
__global__ void __launch_bounds__(256, 2) fuse_mma(
    const __half* __restrict__ up16, const __half* __restrict__ vp16,
    const __half* __restrict__ wp, const float* __restrict__ bp,
    float* __restrict__ out)
{
    extern __shared__ char dsm[];
    uint32_t sb_raw = smem_u32(dsm);
    uint32_t sb = (sb_raw + 1023u) & ~1023u;
    char* smp = dsm + (sb - sb_raw);

    constexpr uint32_t OFF_B = 65536, BBUF = 16384, OFF_UPS = 98304;

    const int bm = blockIdx.x, b = bm >> 5;
    const int tid = threadIdx.x;
    const int wid = tid >> 5, lane = tid & 31;
    const int wm = (wid >> 2) * 64, wn = (wid & 3) * 32;

    const int row = tid >> 1, seg = tid & 1;
    const uint32_t rowoff = (uint32_t)(row * 128 + seg * 64);

    const __half* vrow = vp16 + (size_t)(b * 128 + row) * 256 + seg * 32;
    const __half* w0 = wp + (size_t)row * 256 + seg * 32;              // half 0
    const __half* w1 = wp + (size_t)(128 + row) * 256 + seg * 32;     // half 1

    // ---- prologue: g0=(A0,B00), g1=(A1,B01), g2=(A2), g3=(A3) ----
#pragma unroll
    for (int j = 0; j < 4; j++) {
        uint32_t sw = SWZ(rowoff + j * 16);
        cp16(sb + sw, vrow + j * 8);
        cp16(sb + OFF_B + sw, w0 + j * 8);
    }
    cp_commit();
#pragma unroll
    for (int j = 0; j < 4; j++) {
        uint32_t sw = SWZ(rowoff + j * 16);
        cp16(sb + 16384 + sw, vrow + 64 + j * 8);
        cp16(sb + OFF_B + BBUF + sw, w0 + 64 + j * 8);
    }
    cp_commit();
#pragma unroll
    for (int j = 0; j < 4; j++)
        cp16(sb + 32768 + SWZ(rowoff + j * 16), vrow + 128 + j * 8);
    cp_commit();
#pragma unroll
    for (int j = 0; j < 4; j++)
        cp16(sb + 49152 + SWZ(rowoff + j * 16), vrow + 192 + j * 8);
    cp_commit();

    // ---- up16[bm] -> smem (128 half2) ----
    __half2* ups2 = (__half2*)(smp + OFF_UPS);
    if (tid < 128) ups2[tid] = ((const __half2*)(up16 + (size_t)bm * 256))[tid];

    cp_wait<3>();      // g0 done: A0 + B00
    __syncthreads();   // + ups2 visible

    // ---- hoisted row bases and swizzle bits (kept separate) ----
    uint32_t ra[4], sa[4], rb[2], sbz[2];
#pragma unroll
    for (int mi = 0; mi < 4; mi++) {
        ra[mi] = (uint32_t)((wm + mi * 16 + (lane & 15)) * 128);
        sa[mi] = (ra[mi] >> 3) & 0x70;
    }
#pragma unroll
    for (int np = 0; np < 2; np++) {
        rb[np] = (uint32_t)((wn + np * 16 + (lane & 15)) * 128);
        sbz[np] = (rb[np] >> 3) & 0x70;
    }
    const uint32_t acl = (uint32_t)((lane >> 4) * 16);
    const int lq = lane & 3;
    const int rin = lane >> 2, cin = (lane & 3) * 2;

    float c[4][4][4];

    for (int nh = 0; nh < 2; nh++) {
        const __half* wrow = nh ? w1 : w0;
#pragma unroll
        for (int i = 0; i < 4; i++)
#pragma unroll
            for (int j = 0; j < 4; j++)
#pragma unroll
                for (int q = 0; q < 4; q++) c[i][j][q] = 0.f;

#pragma unroll
        for (int kc = 0; kc < 4; kc++) {
            uint32_t abase = sb + (uint32_t)kc * 16384;
            uint32_t bbase = sb + OFF_B + (uint32_t)(kc & 1) * BBUF;
#pragma unroll
            for (int ks = 0; ks < 4; ks++) {
                const int ksg = kc * 4 + ks;
                const __half2 mul0 = ups2[ksg * 8 + lq];
                const __half2 mul1 = ups2[ksg * 8 + 4 + lq];
                const uint32_t acol = (uint32_t)(ks * 32) + acl;
                uint32_t a[4][4], bfr[4][2];
#pragma unroll
                for (int mi = 0; mi < 4; mi++)
                    ldsm4(a[mi][0], a[mi][1], a[mi][2], a[mi][3],
                          abase + ra[mi] + (acol ^ sa[mi]));
#pragma unroll
                for (int np = 0; np < 2; np++) {
                    uint32_t m0, m1, m2, m3;
                    ldsm4(m0, m1, m2, m3, bbase + rb[np] + (acol ^ sbz[np]));
                    bfr[2 * np][0]     = hmul2u(m0, mul0);
                    bfr[2 * np][1]     = hmul2u(m2, mul1);
                    bfr[2 * np + 1][0] = hmul2u(m1, mul0);
                    bfr[2 * np + 1][1] = hmul2u(m3, mul1);
                }
#pragma unroll
                for (int mi = 0; mi < 4; mi++)
#pragma unroll
                    for (int nj = 0; nj < 4; nj++)
                        mma_f16(c[mi][nj], a[mi], bfr[nj]);
            }
            // pipeline control: refill B buffers for chunks kc+2
            if (kc == 0) {
                __syncthreads();                   // done reading B buf0
#pragma unroll
                for (int j = 0; j < 4; j++)        // B chunk2 -> buf0
                    cp16(sb + OFF_B + SWZ(rowoff + j * 16), wrow + 128 + j * 8);
                cp_commit();
                if (nh == 0) { cp_wait<3>(); __syncthreads(); }  // g1 (A1+B01)
                // nh==1: buf1 (B11) already resident; no wait needed
            } else if (kc == 1) {
                __syncthreads();                   // done reading B buf1
#pragma unroll
                for (int j = 0; j < 4; j++)        // B chunk3 -> buf1
                    cp16(sb + OFF_B + BBUF + SWZ(rowoff + j * 16), wrow + 192 + j * 8);
                cp_commit();
                cp_wait<1>();                      // chunk2 (and A2/A3 on nh0) done
                __syncthreads();
            } else if (kc == 2) {
                cp_wait<0>();                      // chunk3 done
                __syncthreads();
            }
        }

        if (nh == 0) {
            // boundary: fetch half-1 B chunks 0,1 while doing half-0 epilogue
            __syncthreads();                       // all warps done with B bufs
#pragma unroll
            for (int j = 0; j < 4; j++) {
                uint32_t sw = SWZ(rowoff + j * 16);
                cp16(sb + OFF_B + sw, w1 + j * 8);
                cp16(sb + OFF_B + BBUF + sw, w1 + 64 + j * 8);
            }
            cp_commit();
        }

        // ---- epilogue for this half: +bias, relu, store ----
        float* obase = out + (size_t)bm * 128 * 256 + nh * 128;
#pragma unroll
        for (int nj = 0; nj < 4; nj++) {
            const int f = wn + nj * 8 + cin;
            const float b0 = bp[nh * 128 + f], b1 = bp[nh * 128 + f + 1];
#pragma unroll
            for (int mi = 0; mi < 4; mi++) {
                float* p0 = obase + (size_t)(wm + mi * 16 + rin) * 256 + f;
                *(float2*)p0 = make_float2(fmaxf(c[mi][nj][0] + b0, 0.f),
                                           fmaxf(c[mi][nj][1] + b1, 0.f));
                *(float2*)(p0 + 8 * 256) = make_float2(fmaxf(c[mi][nj][2] + b0, 0.f),
                                                       fmaxf(c[mi][nj][3] + b1, 0.f));
            }
        }

        if (nh == 0) {
            cp_wait<0>();      // B10 + B11 resident
            __syncthreads();
        }
    }
}

// -------------------- host launch -------------------------------------------
extern "C" void kernel_launch(void* const* d_in, const int* in_sizes, int n_in,
                              void* d_out, int out_size) {
    const float* u  = (const float*)d_in[0];   // (32,32,1024)
    const float* v  = (const float*)d_in[1];   // (32,128,2048)
    const float* Wu = (const float*)d_in[2];   // (256,1024)
    const float* Wv = (const float*)d_in[3];   // (256,2048)
    const float* Wp = (const float*)d_in[4];   // (256,256)
    const float* bp = (const float*)d_in[5];   // (256,)
    float* out = (float*)d_out;                // (32,32,128,256)

    float *vpp_p, *upp_p;
    __half *up16, *vp16, *u16, *v16, *wu, *wv, *wp;
    cudaGetSymbolAddress((void**)&vpp_p, g_vp_part);
    cudaGetSymbolAddress((void**)&upp_p, g_up_part);
    cudaGetSymbolAddress((void**)&up16, g_up16);
    cudaGetSymbolAddress((void**)&vp16, g_vp16);
    cudaGetSymbolAddress((void**)&u16, g_u16);
    cudaGetSymbolAddress((void**)&v16, g_v16);
    cudaGetSymbolAddress((void**)&wu, g_wu16);
    cudaGetSymbolAddress((void**)&wv, g_wv16);
    cudaGetSymbolAddress((void**)&wp, g_wp16);

    const int PROJ_SMEM = 2 * 32768 + 1024;          // 66560
    const int FUSE_SMEM = 98304 + 512 + 1024;        // 99840
    cudaFuncSetAttribute(proj_mma, cudaFuncAttributeMaxDynamicSharedMemorySize, PROJ_SMEM);
    cudaFuncSetAttribute(fuse_mma, cudaFuncAttributeMaxDynamicSharedMemorySize, FUSE_SMEM);

    const int total = 1024 * 1024 + 4096 * 2048 + 256 * 1024 + 256 * 2048 + 256 * 256;
    prep_cvt<<<(total / 4 + 255) / 256, 256>>>(u, v, Wu, Wv, Wp, u16, v16, wu, wv, wp);
    proj_mma<<<288, 256, PROJ_SMEM>>>(u16, v16, wu, wv, upp_p, vpp_p);
    add_parts<<<1280, 256>>>(vpp_p, upp_p, vp16, up16);
    fuse_mma<<<1024, 256, FUSE_SMEM>>>(up16, vp16, wp, bp, out);
}